// round 16
// baseline (speedup 1.0000x reference)
#include <cuda_runtime.h>
#include <cuda_fp16.h>
#include <math.h>
#include <stdint.h>

#define NN 50000
#define EE 800000
#define DD 128
#define TOT 100000
#define PAD 96
#define LN_EPS 1e-5f
#define NTILES 782          // ceil(TOT/128)

// ---------------- static device scratch (no allocation allowed) -------------
__device__ int   g_cnt[NN];
__device__ int2  g_edge[NN * PAD];     // (col, val fp32 bits)
// z = x @ W in fp16: 16 uint4 (=128 halves) per row
__device__ uint4 g_zh[2 * NN * 16];

// ---------------- helpers -----------------------------------------------------
__device__ __forceinline__ unsigned h2_as_u32(__half2 h) {
    return *reinterpret_cast<unsigned*>(&h);
}
__device__ __forceinline__ __half2 u32_as_h2(unsigned u) {
    return *reinterpret_cast<__half2*>(&u);
}
__device__ __forceinline__ uint32_t smem_u32(const void* p) {
    uint32_t a;
    asm("{ .reg .u64 t; cvta.to.shared.u64 t, %1; cvt.u32.u64 %0, t; }"
        : "=r"(a) : "l"(p));
    return a;
}
#define LDSM4(r0, r1, r2, r3, addr) \
    asm volatile("ldmatrix.sync.aligned.m8n8.x4.shared.b16 {%0,%1,%2,%3}, [%4];" \
                 : "=r"(r0), "=r"(r1), "=r"(r2), "=r"(r3) : "r"(addr))
#define LDSM4T(r0, r1, r2, r3, addr) \
    asm volatile("ldmatrix.sync.aligned.m8n8.x4.trans.shared.b16 {%0,%1,%2,%3}, [%4];" \
                 : "=r"(r0), "=r"(r1), "=r"(r2), "=r"(r3) : "r"(addr))
#define MMA16816(c, a0, a1, a2, a3, b0, b1) \
    asm volatile("mma.sync.aligned.m16n8k16.row.col.f32.f16.f16.f32 " \
                 "{%0,%1,%2,%3}, {%4,%5,%6,%7}, {%8,%9}, {%0,%1,%2,%3};" \
                 : "+f"((c)[0]), "+f"((c)[1]), "+f"((c)[2]), "+f"((c)[3]) \
                 : "r"(a0), "r"(a1), "r"(a2), "r"(a3), "r"(b0), "r"(b1))

// ---------------- 1. HMMA GEMM z = x @ W (fp16) + fused scatter ---------------
// B staged directly from W fp32 [k][n] (coalesced) as fp16 [k][n]; mainloop
// uses ldmatrix.x4.trans so no pre-transpose kernel is needed.
__global__ void __launch_bounds__(256) gemm_mma_kernel(
        const float* __restrict__ x,
        const float* __restrict__ W,
        const int*   __restrict__ rows,
        const int*   __restrict__ cols,
        const float* __restrict__ vals) {
    extern __shared__ char sm[];
    uint32_t smb = smem_u32(sm);
    int tid  = threadIdx.x;
    int w    = tid >> 5;
    int lane = tid & 31;
    size_t row0 = (size_t)blockIdx.x * 128;

    // ---- fused edge scatter: 4 edges/thread (atomics overlap staging)
    {
        int i = (blockIdx.x * 256 + tid) * 4;
        if (i + 3 < EE) {
            int4   r4 = *(const int4*)(rows + i);
            int4   c4 = *(const int4*)(cols + i);
            float4 v4 = *(const float4*)(vals + i);
            int p0 = atomicAdd(&g_cnt[r4.x], 1);
            int p1 = atomicAdd(&g_cnt[r4.y], 1);
            int p2 = atomicAdd(&g_cnt[r4.z], 1);
            int p3 = atomicAdd(&g_cnt[r4.w], 1);
            if (p0 < PAD) g_edge[r4.x * PAD + p0] = make_int2(c4.x, __float_as_int(v4.x));
            if (p1 < PAD) g_edge[r4.y * PAD + p1] = make_int2(c4.y, __float_as_int(v4.y));
            if (p2 < PAD) g_edge[r4.z * PAD + p2] = make_int2(c4.z, __float_as_int(v4.z));
            if (p3 < PAD) g_edge[r4.w * PAD + p3] = make_int2(c4.w, __float_as_int(v4.w));
        } else {
            for (; i < EE; i++) {
                int r = rows[i];
                int p = atomicAdd(&g_cnt[r], 1);
                if (p < PAD) g_edge[r * PAD + p] = make_int2(cols[i], __float_as_int(vals[i]));
            }
        }
    }

    // ---- stage A = x tile -> fp16, swizzled: chunk(r,kc) at r*256 + ((kc^(r&7))*16)
    const float4* x4 = (const float4*)x;
    #pragma unroll
    for (int idx = tid; idx < 128 * 16; idx += 256) {
        int r = idx >> 4, kc = idx & 15;
        size_t gr = row0 + (size_t)r;
        if (gr >= TOT) gr = 0;
        float4 f0 = x4[gr * 32 + kc * 2];
        float4 f1 = x4[gr * 32 + kc * 2 + 1];
        uint4 h;
        h.x = h2_as_u32(__floats2half2_rn(f0.x, f0.y));
        h.y = h2_as_u32(__floats2half2_rn(f0.z, f0.w));
        h.z = h2_as_u32(__floats2half2_rn(f1.x, f1.y));
        h.w = h2_as_u32(__floats2half2_rn(f1.z, f1.w));
        *(uint4*)(sm + r * 256 + ((kc ^ (r & 7)) << 4)) = h;
    }
    // ---- stage B = W fp16 [k][n] natural layout (coalesced fp32 read), +32KB
    const float4* W4 = (const float4*)W;
    #pragma unroll
    for (int idx = tid; idx < 128 * 16; idx += 256) {
        int r = idx >> 4, c = idx & 15;           // r = k row, c = 16B chunk (8 n)
        float4 f0 = W4[r * 32 + c * 2];
        float4 f1 = W4[r * 32 + c * 2 + 1];
        uint4 h;
        h.x = h2_as_u32(__floats2half2_rn(f0.x, f0.y));
        h.y = h2_as_u32(__floats2half2_rn(f0.z, f0.w));
        h.z = h2_as_u32(__floats2half2_rn(f1.x, f1.y));
        h.w = h2_as_u32(__floats2half2_rn(f1.z, f1.w));
        *(uint4*)(sm + 32768 + r * 256 + ((c ^ (r & 7)) << 4)) = h;
    }
    __syncthreads();

    // ---- mma mainloop
    int quad = lane >> 3, li = lane & 7;
    int rowA = (w << 4) + ((quad & 1) << 3) + li;
    int kqa  = quad >> 1;
    int klnB  = lane & 15;        // B: k-row within 16 for this lane
    int nhalf = lane >> 4;        // B: n-octet selector (0: n+0..7, 1: n+8..15)

    float acc[16][4];
    #pragma unroll
    for (int nt = 0; nt < 16; nt++)
        #pragma unroll
        for (int q = 0; q < 4; q++) acc[nt][q] = 0.f;

    #pragma unroll
    for (int ks = 0; ks < 8; ks++) {
        uint32_t a0, a1, a2, a3;
        uint32_t addrA = smb + rowA * 256 + ((((ks << 1) + kqa) ^ (rowA & 7)) << 4);
        LDSM4(a0, a1, a2, a3, addrA);
        int krow = (ks << 4) + klnB;
        #pragma unroll
        for (int p = 0; p < 8; p++) {
            int cb = (p << 1) + nhalf;   // chunk covering n [16p + 8*nhalf, +8)
            uint32_t addrB = smb + 32768 + krow * 256 + ((cb ^ (krow & 7)) << 4);
            uint32_t b0, b1, b2, b3;
            LDSM4T(b0, b1, b2, b3, addrB);
            MMA16816(acc[2 * p],     a0, a1, a2, a3, b0, b1);
            MMA16816(acc[2 * p + 1], a0, a1, a2, a3, b2, b3);
        }
    }

    // ---- epilogue: restage z through smem (A area, conflict-free XOR layout),
    //      then fully-coalesced uint4 global stores.
    __syncthreads();
    {
        int gid = lane >> 2, tig = lane & 3;
        int rlo = (w << 4) + gid;
        int rhi = rlo + 8;
        #pragma unroll
        for (int nt = 0; nt < 16; nt++) {
            *(uint32_t*)(sm + rlo * 256 + ((nt ^ (rlo & 7)) << 4) + tig * 4) =
                h2_as_u32(__floats2half2_rn(acc[nt][0], acc[nt][1]));
            *(uint32_t*)(sm + rhi * 256 + ((nt ^ (rhi & 7)) << 4) + tig * 4) =
                h2_as_u32(__floats2half2_rn(acc[nt][2], acc[nt][3]));
        }
    }
    __syncthreads();
    #pragma unroll
    for (int idx = tid; idx < 128 * 16; idx += 256) {
        int r = idx >> 4, c = idx & 15;
        size_t gr = row0 + (size_t)r;
        if (gr < TOT)
            g_zh[gr * 16 + c] = *(uint4*)(sm + r * 256 + ((c ^ (r & 7)) << 4));
    }
}

// ---------------- 2. SpMM over z + bias + LN + GELU (R12 proven form) --------
__device__ __forceinline__ float gelu_exact(float v) {
    return 0.5f * v * (1.0f + erff(v * 0.70710678118654752f));
}
__device__ __forceinline__ void hfma8(float* a, float v, uint4 u) {
    float2 f0 = __half22float2(u32_as_h2(u.x));
    float2 f1 = __half22float2(u32_as_h2(u.y));
    float2 f2 = __half22float2(u32_as_h2(u.z));
    float2 f3 = __half22float2(u32_as_h2(u.w));
    a[0] = fmaf(v, f0.x, a[0]); a[1] = fmaf(v, f0.y, a[1]);
    a[2] = fmaf(v, f1.x, a[2]); a[3] = fmaf(v, f1.y, a[3]);
    a[4] = fmaf(v, f2.x, a[4]); a[5] = fmaf(v, f2.y, a[5]);
    a[6] = fmaf(v, f3.x, a[6]); a[7] = fmaf(v, f3.y, a[7]);
}

__global__ void __launch_bounds__(256) spmm_ln_gelu_kernel(
        float* __restrict__ out,
        const float* __restrict__ bias,
        const float* __restrict__ gamma,
        const float* __restrict__ beta) {
    int node = (blockIdx.x * 256 + threadIdx.x) >> 5;
    int lane = threadIdx.x & 31;
    int half = lane >> 4;
    int hl   = lane & 15;
    if (node >= NN) return;
    int cnt = min(g_cnt[node], PAD);
    const int2* ep = g_edge + (size_t)node * PAD;
    const uint4* zb = g_zh + (size_t)half * (NN * 16);

    float a[8] = {0.f, 0.f, 0.f, 0.f, 0.f, 0.f, 0.f, 0.f};

    int j = 0;
    for (; j + 4 <= cnt; j += 4) {
        int4 ea = *(const int4*)(ep + j);
        int4 eb = *(const int4*)(ep + j + 2);
        uint4 u0 = zb[(unsigned)(ea.x * 16 + hl)];
        uint4 u1 = zb[(unsigned)(ea.z * 16 + hl)];
        uint4 u2 = zb[(unsigned)(eb.x * 16 + hl)];
        uint4 u3 = zb[(unsigned)(eb.z * 16 + hl)];
        hfma8(a, __int_as_float(ea.y), u0);
        hfma8(a, __int_as_float(ea.w), u1);
        hfma8(a, __int_as_float(eb.y), u2);
        hfma8(a, __int_as_float(eb.w), u3);
    }
    for (; j < cnt; j++) {
        int2 e = ep[j];
        uint4 u = zb[(unsigned)(e.x * 16 + hl)];
        hfma8(a, __int_as_float(e.y), u);
    }

    float4 b0 = ((const float4*)bias )[hl * 2], b1 = ((const float4*)bias )[hl * 2 + 1];
    float4 g0 = ((const float4*)gamma)[hl * 2], g1 = ((const float4*)gamma)[hl * 2 + 1];
    float4 e0 = ((const float4*)beta )[hl * 2], e1 = ((const float4*)beta )[hl * 2 + 1];
    a[0] += b0.x; a[1] += b0.y; a[2] += b0.z; a[3] += b0.w;
    a[4] += b1.x; a[5] += b1.y; a[6] += b1.z; a[7] += b1.w;

    float s = 0.f, ss = 0.f;
    #pragma unroll
    for (int c = 0; c < 8; c++) { s += a[c]; ss += a[c] * a[c]; }
    #pragma unroll
    for (int o = 8; o > 0; o >>= 1) {
        s  += __shfl_xor_sync(0xffffffffu, s,  o);
        ss += __shfl_xor_sync(0xffffffffu, ss, o);
    }
    const float inv_d = 1.0f / (float)DD;
    float mu  = s * inv_d;
    float var = ss * inv_d - mu * mu;
    float rs  = rsqrtf(var + LN_EPS);

    float4 r0, r1;
    r0.x = gelu_exact((a[0] - mu) * rs * g0.x + e0.x);
    r0.y = gelu_exact((a[1] - mu) * rs * g0.y + e0.y);
    r0.z = gelu_exact((a[2] - mu) * rs * g0.z + e0.z);
    r0.w = gelu_exact((a[3] - mu) * rs * g0.w + e0.w);
    r1.x = gelu_exact((a[4] - mu) * rs * g1.x + e1.x);
    r1.y = gelu_exact((a[5] - mu) * rs * g1.y + e1.y);
    r1.z = gelu_exact((a[6] - mu) * rs * g1.z + e1.z);
    r1.w = gelu_exact((a[7] - mu) * rs * g1.w + e1.w);

    size_t grow = (size_t)half * NN + (size_t)node;
    float4* out4 = (float4*)out;
    out4[grow * 32 + hl * 2]     = r0;
    out4[grow * 32 + hl * 2 + 1] = r1;
}

// ---------------- launch ------------------------------------------------------
extern "C" void kernel_launch(void* const* d_in, const int* in_sizes, int n_in,
                              void* d_out, int out_size) {
    const float* x     = (const float*)d_in[0];
    const int*   rows  = (const int*)  d_in[1];
    const int*   cols  = (const int*)  d_in[2];
    const float* vals  = (const float*)d_in[3];
    const float* W     = (const float*)d_in[4];
    const float* bias  = (const float*)d_in[5];
    const float* gamma = (const float*)d_in[6];
    const float* beta  = (const float*)d_in[7];
    float* out = (float*)d_out;

    void* cnt_ptr = nullptr;
    cudaGetSymbolAddress(&cnt_ptr, g_cnt);
    cudaMemsetAsync(cnt_ptr, 0, NN * sizeof(int));

    const int smem_bytes = 65536;
    cudaFuncSetAttribute(gemm_mma_kernel,
                         cudaFuncAttributeMaxDynamicSharedMemorySize, smem_bytes);
    gemm_mma_kernel<<<NTILES, 256, smem_bytes>>>(x, W, rows, cols, vals);

    spmm_ln_gelu_kernel<<<(NN * 32 + 255) / 256, 256>>>(out, bias, gamma, beta);
}

// round 17
// speedup vs baseline: 1.0402x; 1.0402x over previous
#include <cuda_runtime.h>
#include <cuda_fp16.h>
#include <math.h>
#include <stdint.h>

#define NN 50000
#define EE 800000
#define DD 128
#define TOT 100000
#define PAD 96
#define LN_EPS 1e-5f
#define NTILES 782          // ceil(TOT/128)

// ---------------- static device scratch (no allocation allowed) -------------
__device__ int   g_cnt[NN];
__device__ int2  g_edge[NN * PAD];     // (col*16, val fp32 bits)
__device__ uint4 g_wh4[DD * DD / 8];   // W^T as fp16 [n][k] row-major
// z = x @ W in fp16: 16 uint4 (=128 halves) per row
__device__ uint4 g_zh[2 * NN * 16];

// ---------------- helpers -----------------------------------------------------
__device__ __forceinline__ unsigned h2_as_u32(__half2 h) {
    return *reinterpret_cast<unsigned*>(&h);
}
__device__ __forceinline__ __half2 u32_as_h2(unsigned u) {
    return *reinterpret_cast<__half2*>(&u);
}
__device__ __forceinline__ uint32_t smem_u32(const void* p) {
    uint32_t a;
    asm("{ .reg .u64 t; cvta.to.shared.u64 t, %1; cvt.u32.u64 %0, t; }"
        : "=r"(a) : "l"(p));
    return a;
}
#define LDSM4(r0, r1, r2, r3, addr) \
    asm volatile("ldmatrix.sync.aligned.m8n8.x4.shared.b16 {%0,%1,%2,%3}, [%4];" \
                 : "=r"(r0), "=r"(r1), "=r"(r2), "=r"(r3) : "r"(addr))
#define MMA16816(c, a0, a1, a2, a3, b0, b1) \
    asm volatile("mma.sync.aligned.m16n8k16.row.col.f32.f16.f16.f32 " \
                 "{%0,%1,%2,%3}, {%4,%5,%6,%7}, {%8,%9}, {%0,%1,%2,%3};" \
                 : "+f"((c)[0]), "+f"((c)[1]), "+f"((c)[2]), "+f"((c)[3]) \
                 : "r"(a0), "r"(a1), "r"(a2), "r"(a3), "r"(b0), "r"(b1))

// ---------------- 0. zero counters + transpose W to fp16 [n][k] --------------
__global__ void __launch_bounds__(256) wtrans_zero_kernel(const float* __restrict__ W) {
    int t = blockIdx.x * 256 + threadIdx.x;    // 51200 threads
    if (t < NN) g_cnt[t] = 0;
    if (t < DD * DD) {
        int n = t >> 7, k = t & 127;
        ((__half*)g_wh4)[t] = __float2half_rn(W[k * DD + n]);
    }
}

// ---------------- 1. HMMA GEMM z = x @ W (fp16) + fused scatter ---------------
__global__ void __launch_bounds__(256) gemm_mma_kernel(
        const float* __restrict__ x,
        const int*   __restrict__ rows,
        const int*   __restrict__ cols,
        const float* __restrict__ vals) {
    extern __shared__ char sm[];
    uint32_t smb = smem_u32(sm);
    int tid  = threadIdx.x;
    int w    = tid >> 5;
    int lane = tid & 31;
    size_t row0 = (size_t)blockIdx.x * 128;

    // ---- fused edge scatter: 4 edges/thread (atomics overlap staging)
    //      col stored pre-scaled by 16 (uint4 index units) for the spmm.
    {
        int i = (blockIdx.x * 256 + tid) * 4;
        if (i + 3 < EE) {
            int4   r4 = *(const int4*)(rows + i);
            int4   c4 = *(const int4*)(cols + i);
            float4 v4 = *(const float4*)(vals + i);
            int p0 = atomicAdd(&g_cnt[r4.x], 1);
            int p1 = atomicAdd(&g_cnt[r4.y], 1);
            int p2 = atomicAdd(&g_cnt[r4.z], 1);
            int p3 = atomicAdd(&g_cnt[r4.w], 1);
            if (p0 < PAD) g_edge[r4.x * PAD + p0] = make_int2(c4.x * 16, __float_as_int(v4.x));
            if (p1 < PAD) g_edge[r4.y * PAD + p1] = make_int2(c4.y * 16, __float_as_int(v4.y));
            if (p2 < PAD) g_edge[r4.z * PAD + p2] = make_int2(c4.z * 16, __float_as_int(v4.z));
            if (p3 < PAD) g_edge[r4.w * PAD + p3] = make_int2(c4.w * 16, __float_as_int(v4.w));
        } else {
            for (; i < EE; i++) {
                int r = rows[i];
                int p = atomicAdd(&g_cnt[r], 1);
                if (p < PAD) g_edge[r * PAD + p] = make_int2(cols[i] * 16, __float_as_int(vals[i]));
            }
        }
    }

    // ---- stage A = x tile -> fp16, swizzled: chunk(r,kc) at r*256 + ((kc^(r&7))*16)
    const float4* x4 = (const float4*)x;
    #pragma unroll
    for (int idx = tid; idx < 128 * 16; idx += 256) {
        int r = idx >> 4, kc = idx & 15;
        size_t gr = row0 + (size_t)r;
        if (gr >= TOT) gr = 0;
        float4 f0 = x4[gr * 32 + kc * 2];
        float4 f1 = x4[gr * 32 + kc * 2 + 1];
        uint4 h;
        h.x = h2_as_u32(__floats2half2_rn(f0.x, f0.y));
        h.y = h2_as_u32(__floats2half2_rn(f0.z, f0.w));
        h.z = h2_as_u32(__floats2half2_rn(f1.x, f1.y));
        h.w = h2_as_u32(__floats2half2_rn(f1.z, f1.w));
        *(uint4*)(sm + r * 256 + ((kc ^ (r & 7)) << 4)) = h;
    }
    // ---- stage B = W^T fp16 [n][k], same swizzle, at +32KB
    #pragma unroll
    for (int idx = tid; idx < 128 * 16; idx += 256) {
        int n = idx >> 4, kc = idx & 15;
        *(uint4*)(sm + 32768 + n * 256 + ((kc ^ (n & 7)) << 4)) = g_wh4[idx];
    }
    __syncthreads();

    // ---- mma mainloop
    int quad = lane >> 3, li = lane & 7;
    int rowA = (w << 4) + ((quad & 1) << 3) + li;
    int kqa  = quad >> 1;
    int nqb  = (quad >> 1) << 3;
    int kqb  = quad & 1;

    float acc[16][4];
    #pragma unroll
    for (int nt = 0; nt < 16; nt++)
        #pragma unroll
        for (int q = 0; q < 4; q++) acc[nt][q] = 0.f;

    #pragma unroll
    for (int ks = 0; ks < 8; ks++) {
        uint32_t a0, a1, a2, a3;
        uint32_t addrA = smb + rowA * 256 + ((((ks << 1) + kqa) ^ (rowA & 7)) << 4);
        LDSM4(a0, a1, a2, a3, addrA);
        #pragma unroll
        for (int p = 0; p < 8; p++) {
            int nrow = (p << 4) + nqb + li;
            uint32_t addrB = smb + 32768 + nrow * 256
                           + ((((ks << 1) + kqb) ^ (nrow & 7)) << 4);
            uint32_t b0, b1, b2, b3;
            LDSM4(b0, b1, b2, b3, addrB);
            MMA16816(acc[2 * p],     a0, a1, a2, a3, b0, b1);
            MMA16816(acc[2 * p + 1], a0, a1, a2, a3, b2, b3);
        }
    }

    // ---- epilogue: restage z through smem (A area, conflict-free XOR layout),
    //      then fully-coalesced uint4 global stores.
    __syncthreads();
    {
        int gid = lane >> 2, tig = lane & 3;
        int rlo = (w << 4) + gid;
        int rhi = rlo + 8;
        #pragma unroll
        for (int nt = 0; nt < 16; nt++) {
            *(uint32_t*)(sm + rlo * 256 + ((nt ^ (rlo & 7)) << 4) + tig * 4) =
                h2_as_u32(__floats2half2_rn(acc[nt][0], acc[nt][1]));
            *(uint32_t*)(sm + rhi * 256 + ((nt ^ (rhi & 7)) << 4) + tig * 4) =
                h2_as_u32(__floats2half2_rn(acc[nt][2], acc[nt][3]));
        }
    }
    __syncthreads();
    #pragma unroll
    for (int idx = tid; idx < 128 * 16; idx += 256) {
        int r = idx >> 4, c = idx & 15;
        size_t gr = row0 + (size_t)r;
        if (gr < TOT)
            g_zh[gr * 16 + c] = *(uint4*)(sm + r * 256 + ((c ^ (r & 7)) << 4));
    }
}

// ---------------- 2. SpMM over z + bias + LN + GELU --------------------------
__device__ __forceinline__ float gelu_exact(float v) {
    return 0.5f * v * (1.0f + erff(v * 0.70710678118654752f));
}
__device__ __forceinline__ void hfma8(float* a, float v, uint4 u) {
    float2 f0 = __half22float2(u32_as_h2(u.x));
    float2 f1 = __half22float2(u32_as_h2(u.y));
    float2 f2 = __half22float2(u32_as_h2(u.z));
    float2 f3 = __half22float2(u32_as_h2(u.w));
    a[0] = fmaf(v, f0.x, a[0]); a[1] = fmaf(v, f0.y, a[1]);
    a[2] = fmaf(v, f1.x, a[2]); a[3] = fmaf(v, f1.y, a[3]);
    a[4] = fmaf(v, f2.x, a[4]); a[5] = fmaf(v, f2.y, a[5]);
    a[6] = fmaf(v, f3.x, a[6]); a[7] = fmaf(v, f3.y, a[7]);
}

__global__ void __launch_bounds__(256) spmm_ln_gelu_kernel(
        float* __restrict__ out,
        const float* __restrict__ bias,
        const float* __restrict__ gamma,
        const float* __restrict__ beta) {
    int node = (blockIdx.x * 256 + threadIdx.x) >> 5;
    int lane = threadIdx.x & 31;
    int half = lane >> 4;
    int hl   = lane & 15;
    if (node >= NN) return;
    int cnt = min(g_cnt[node], PAD);
    const int2* ep = g_edge + (size_t)node * PAD;
    const uint4* zb = g_zh + (size_t)half * (NN * 16);

    float a[8] = {0.f, 0.f, 0.f, 0.f, 0.f, 0.f, 0.f, 0.f};

    int j = 0;
    for (; j + 4 <= cnt; j += 4) {
        int4 ea = *(const int4*)(ep + j);
        int4 eb = *(const int4*)(ep + j + 2);
        uint4 u0 = zb[(unsigned)(ea.x + hl)];   // col pre-scaled by 16
        uint4 u1 = zb[(unsigned)(ea.z + hl)];
        uint4 u2 = zb[(unsigned)(eb.x + hl)];
        uint4 u3 = zb[(unsigned)(eb.z + hl)];
        hfma8(a, __int_as_float(ea.y), u0);
        hfma8(a, __int_as_float(ea.w), u1);
        hfma8(a, __int_as_float(eb.y), u2);
        hfma8(a, __int_as_float(eb.w), u3);
    }
    for (; j < cnt; j++) {
        int2 e = ep[j];
        uint4 u = zb[(unsigned)(e.x + hl)];
        hfma8(a, __int_as_float(e.y), u);
    }

    float4 b0 = ((const float4*)bias )[hl * 2], b1 = ((const float4*)bias )[hl * 2 + 1];
    float4 g0 = ((const float4*)gamma)[hl * 2], g1 = ((const float4*)gamma)[hl * 2 + 1];
    float4 e0 = ((const float4*)beta )[hl * 2], e1 = ((const float4*)beta )[hl * 2 + 1];
    a[0] += b0.x; a[1] += b0.y; a[2] += b0.z; a[3] += b0.w;
    a[4] += b1.x; a[5] += b1.y; a[6] += b1.z; a[7] += b1.w;

    float s = 0.f, ss = 0.f;
    #pragma unroll
    for (int c = 0; c < 8; c++) { s += a[c]; ss += a[c] * a[c]; }
    #pragma unroll
    for (int o = 8; o > 0; o >>= 1) {
        s  += __shfl_xor_sync(0xffffffffu, s,  o);
        ss += __shfl_xor_sync(0xffffffffu, ss, o);
    }
    const float inv_d = 1.0f / (float)DD;
    float mu  = s * inv_d;
    float var = ss * inv_d - mu * mu;
    float rs  = rsqrtf(var + LN_EPS);

    float4 r0, r1;
    r0.x = gelu_exact((a[0] - mu) * rs * g0.x + e0.x);
    r0.y = gelu_exact((a[1] - mu) * rs * g0.y + e0.y);
    r0.z = gelu_exact((a[2] - mu) * rs * g0.z + e0.z);
    r0.w = gelu_exact((a[3] - mu) * rs * g0.w + e0.w);
    r1.x = gelu_exact((a[4] - mu) * rs * g1.x + e1.x);
    r1.y = gelu_exact((a[5] - mu) * rs * g1.y + e1.y);
    r1.z = gelu_exact((a[6] - mu) * rs * g1.z + e1.z);
    r1.w = gelu_exact((a[7] - mu) * rs * g1.w + e1.w);

    size_t grow = (size_t)half * NN + (size_t)node;
    float4* out4 = (float4*)out;
    out4[grow * 32 + hl * 2]     = r0;
    out4[grow * 32 + hl * 2 + 1] = r1;
}

// ---------------- launch ------------------------------------------------------
extern "C" void kernel_launch(void* const* d_in, const int* in_sizes, int n_in,
                              void* d_out, int out_size) {
    const float* x     = (const float*)d_in[0];
    const int*   rows  = (const int*)  d_in[1];
    const int*   cols  = (const int*)  d_in[2];
    const float* vals  = (const float*)d_in[3];
    const float* W     = (const float*)d_in[4];
    const float* bias  = (const float*)d_in[5];
    const float* gamma = (const float*)d_in[6];
    const float* beta  = (const float*)d_in[7];
    float* out = (float*)d_out;

    wtrans_zero_kernel<<<200, 256>>>(W);

    const int smem_bytes = 65536;
    cudaFuncSetAttribute(gemm_mma_kernel,
                         cudaFuncAttributeMaxDynamicSharedMemorySize, smem_bytes);
    gemm_mma_kernel<<<NTILES, 256, smem_bytes>>>(x, rows, cols, vals);

    spmm_ln_gelu_kernel<<<(NN * 32 + 255) / 256, 256>>>(out, bias, gamma, beta);
}